// round 3
// baseline (speedup 1.0000x reference)
#include <cuda_runtime.h>
#include <cstdint>

// Problem constants (fixed by the reference)
#define NN 50000
#define EE 800000
#define IN_C 512
#define HID_C 128
#define OUT_C 256

// Scratch (allocation-free rule: __device__ globals)
__device__ float g_h1[(size_t)NN * HID_C];    // x @ w1^T
__device__ float g_agg1[(size_t)NN * HID_C];  // scatter target layer1 (init to b1)
__device__ float g_h2[(size_t)NN * OUT_C];    // relu(agg1) @ w2^T

// ---------------------------------------------------------------------------
// Classic 128x128x8 SGEMM computing C[m][n] = sum_k A[m][k] * W[n][k]
// (W in torch Linear layout [N,K] row-major, i.e. B = W^T implicitly)
// Optional ReLU applied to A elements on load (fuses layer-1 activation).
// ---------------------------------------------------------------------------
template <bool RELU_IN>
__global__ __launch_bounds__(256)
void sgemm_wt(const float* __restrict__ A, const float* __restrict__ W,
              float* __restrict__ C, int M, int N, int K) {
    constexpr int BM = 128, BN = 128, BK = 8, TM = 8, TN = 8;
    __shared__ float As[BK][BM];
    __shared__ float Bs[BK][BN];

    const int bm = blockIdx.x * BM;
    const int bn = blockIdx.y * BN;
    const int tid = threadIdx.x;          // 0..255
    const int tx = tid & 15;              // 16 x 16 thread grid
    const int ty = tid >> 4;

    float acc[TM][TN];
#pragma unroll
    for (int i = 0; i < TM; i++)
#pragma unroll
        for (int j = 0; j < TN; j++) acc[i][j] = 0.0f;

    for (int k0 = 0; k0 < K; k0 += BK) {
        // Load A tile: 128 rows x 8 k  (1024 elems, 4 per thread)
#pragma unroll
        for (int i = 0; i < 4; i++) {
            int idx = tid + i * 256;
            int row = idx >> 3;       // 0..127
            int col = idx & 7;        // 0..7
            int gr = bm + row;
            float v = 0.0f;
            if (gr < M) {
                v = A[(size_t)gr * K + k0 + col];
                if (RELU_IN) v = fmaxf(v, 0.0f);
            }
            As[col][row] = v;
        }
        // Load W tile: 128 n-rows x 8 k
#pragma unroll
        for (int i = 0; i < 4; i++) {
            int idx = tid + i * 256;
            int n = idx >> 3;
            int k = idx & 7;
            Bs[k][n] = W[(size_t)(bn + n) * K + k0 + k];
        }
        __syncthreads();

#pragma unroll
        for (int kk = 0; kk < BK; kk++) {
            float a[TM], b[TN];
#pragma unroll
            for (int i = 0; i < TM; i++) a[i] = As[kk][ty * TM + i];
#pragma unroll
            for (int j = 0; j < TN; j++) b[j] = Bs[kk][tx * TN + j];
#pragma unroll
            for (int i = 0; i < TM; i++)
#pragma unroll
                for (int j = 0; j < TN; j++) acc[i][j] = fmaf(a[i], b[j], acc[i][j]);
        }
        __syncthreads();
    }

#pragma unroll
    for (int i = 0; i < TM; i++) {
        int gr = bm + ty * TM + i;
        if (gr >= M) continue;
        float* crow = C + (size_t)gr * N + bn + tx * TN;
#pragma unroll
        for (int j = 0; j < TN; j += 4) {
            float4 v = make_float4(acc[i][j], acc[i][j + 1], acc[i][j + 2], acc[i][j + 3]);
            *reinterpret_cast<float4*>(crow + j) = v;
        }
    }
}

// ---------------------------------------------------------------------------
// Initialize aggregation buffer with the broadcast bias (out[n][c] = b[c]).
// C must be a power of two.
// ---------------------------------------------------------------------------
__global__ void init_bias(float* __restrict__ out, const float* __restrict__ b,
                          int total, int cmask) {
    int i = blockIdx.x * blockDim.x + threadIdx.x;
    int stride = gridDim.x * blockDim.x;
    for (; i < total; i += stride) out[i] = b[i & cmask];
}

// ---------------------------------------------------------------------------
// Edge scatter: for each edge e, AGG[dst[e]] += H[src[e]]   (row of C4 float4)
// One warp per edge; lane handles float4 chunks; vector red (no return).
// edge_index arrives as int32 (harness dtype set: float32/int32/bf16).
// ---------------------------------------------------------------------------
template <int C4>
__global__ __launch_bounds__(256)
void scatter_add(const float4* __restrict__ H, const int* __restrict__ ei,
                 float4* __restrict__ AGG, int E) {
    const int warp = (blockIdx.x * blockDim.x + threadIdx.x) >> 5;
    const int lane = threadIdx.x & 31;
    const int nwarps = (gridDim.x * blockDim.x) >> 5;
    const int* __restrict__ src = ei;
    const int* __restrict__ dst = ei + E;

    for (int e = warp; e < E; e += nwarps) {
        const int s = src[e];
        const int d = dst[e];
        // Safety guard: degrade to numeric error (not a crash) if dtype
        // hypothesis is wrong. Never triggers with valid int32 indices.
        if ((unsigned)s >= NN || (unsigned)d >= NN) continue;
        const float4* __restrict__ hs = H + (size_t)s * C4;
        float4* __restrict__ ag = AGG + (size_t)d * C4;
#pragma unroll
        for (int c = lane; c < C4; c += 32) {
            float4 v = hs[c];
            asm volatile(
                "red.global.add.v4.f32 [%0], {%1, %2, %3, %4};"
                :: "l"(ag + c), "f"(v.x), "f"(v.y), "f"(v.z), "f"(v.w)
                : "memory");
        }
    }
}

extern "C" void kernel_launch(void* const* d_in, const int* in_sizes, int n_in,
                              void* d_out, int out_size) {
    const float* x = (const float*)d_in[0];
    const int* edge_index = (const int*)d_in[1];
    const float* w1 = (const float*)d_in[2];
    const float* b1 = (const float*)d_in[3];
    const float* w2 = (const float*)d_in[4];
    const float* b2 = (const float*)d_in[5];
    float* out = (float*)d_out;

    float* h1; cudaGetSymbolAddress((void**)&h1, g_h1);
    float* agg1; cudaGetSymbolAddress((void**)&agg1, g_agg1);
    float* h2; cudaGetSymbolAddress((void**)&h2, g_h2);

    // Layer 1 GEMM: h1 = x @ w1^T   [50000,128]
    {
        dim3 grid((NN + 127) / 128, HID_C / 128);
        sgemm_wt<false><<<grid, 256>>>(x, w1, h1, NN, HID_C, IN_C);
    }
    // agg1 = broadcast(b1)
    init_bias<<<1024, 256>>>(agg1, b1, NN * HID_C, HID_C - 1);
    // agg1[dst] += h1[src]
    scatter_add<HID_C / 4><<<2048, 256>>>((const float4*)h1, edge_index,
                                          (float4*)agg1, EE);
    // Layer 2 GEMM: h2 = relu(agg1) @ w2^T   [50000,256]
    {
        dim3 grid((NN + 127) / 128, OUT_C / 128);
        sgemm_wt<true><<<grid, 256>>>(agg1, w2, h2, NN, OUT_C, HID_C);
    }
    // out = broadcast(b2)
    init_bias<<<1024, 256>>>(out, b2, NN * OUT_C, OUT_C - 1);
    // out[dst] += h2[src]
    scatter_add<OUT_C / 4><<<2048, 256>>>((const float4*)h2, edge_index,
                                          (float4*)out, EE);
}

// round 4
// speedup vs baseline: 2.2053x; 2.2053x over previous
#include <cuda_runtime.h>
#include <cstdint>

// Problem constants (fixed by the reference)
#define NN 50000
#define EE 800000
#define IN_C 512
#define HID_C 128
#define OUT_C 256

// Scratch (allocation-free rule: __device__ globals)
__device__ float g_h1[(size_t)NN * HID_C];    // x @ w1^T
__device__ float g_agg1[(size_t)NN * HID_C];  // A*h1 + b1
__device__ float g_agg2[(size_t)NN * HID_C];  // A*relu(agg1)   (layer-2 scatter, 128 cols)

// ---------------------------------------------------------------------------
// TF32 tensor-core GEMM:  C[m][n] = sum_k A[m][k] * W[n][k]  (+ bias[n])
// W in torch Linear layout [N,K] row-major (acts as B^T; matches mma row.col).
// BM=128, BN=64, BK=32; 8 warps in 4(M) x 2(N); warp tile 32x32; mma m16n8k8.
// ---------------------------------------------------------------------------
__device__ __forceinline__ uint32_t f2tf32(float f) {
    uint32_t r;
    asm("cvt.rna.tf32.f32 %0, %1;" : "=r"(r) : "f"(f));
    return r;
}

template <int K, int NTOT, bool BIAS>
__global__ __launch_bounds__(256)
void gemm_tf32(const float* __restrict__ A, const float* __restrict__ W,
               const float* __restrict__ bias, float* __restrict__ C, int M) {
    constexpr int BM = 128, BN = 64, BK = 32, LDS = BK + 4;  // stride 36 floats
    __shared__ uint32_t As[BM][LDS];
    __shared__ uint32_t Bs[BN][LDS];

    const int tid = threadIdx.x;
    const int lane = tid & 31;
    const int wid = tid >> 5;
    const int warp_m = wid >> 1;   // 0..3
    const int warp_n = wid & 1;    // 0..1
    const int bm = blockIdx.x * BM;
    const int bn = blockIdx.y * BN;

    float acc[2][4][4];
#pragma unroll
    for (int mf = 0; mf < 2; mf++)
#pragma unroll
        for (int nf = 0; nf < 4; nf++)
#pragma unroll
            for (int r = 0; r < 4; r++) acc[mf][nf][r] = 0.0f;

    for (int k0 = 0; k0 < K; k0 += BK) {
        // A tile: 128 rows x 8 float4 = 1024 float4 -> 4 per thread
#pragma unroll
        for (int i = 0; i < 4; i++) {
            int idx = tid + i * 256;
            int row = idx >> 3;
            int c4 = (idx & 7) * 4;
            float4 v = make_float4(0.f, 0.f, 0.f, 0.f);
            if (bm + row < M)
                v = *reinterpret_cast<const float4*>(A + (size_t)(bm + row) * K + k0 + c4);
            As[row][c4 + 0] = f2tf32(v.x);
            As[row][c4 + 1] = f2tf32(v.y);
            As[row][c4 + 2] = f2tf32(v.z);
            As[row][c4 + 3] = f2tf32(v.w);
        }
        // B tile: 64 rows x 8 float4 = 512 -> 2 per thread
#pragma unroll
        for (int i = 0; i < 2; i++) {
            int idx = tid + i * 256;
            int row = idx >> 3;
            int c4 = (idx & 7) * 4;
            float4 v = *reinterpret_cast<const float4*>(W + (size_t)(bn + row) * K + k0 + c4);
            Bs[row][c4 + 0] = f2tf32(v.x);
            Bs[row][c4 + 1] = f2tf32(v.y);
            Bs[row][c4 + 2] = f2tf32(v.z);
            Bs[row][c4 + 3] = f2tf32(v.w);
        }
        __syncthreads();

#pragma unroll
        for (int ks = 0; ks < BK / 8; ks++) {
            const int kb = ks * 8;
            uint32_t a[2][4], b[4][2];
#pragma unroll
            for (int mf = 0; mf < 2; mf++) {
                int mr = warp_m * 32 + mf * 16 + (lane >> 2);
                int kc = kb + (lane & 3);
                a[mf][0] = As[mr][kc];
                a[mf][1] = As[mr + 8][kc];
                a[mf][2] = As[mr][kc + 4];
                a[mf][3] = As[mr + 8][kc + 4];
            }
#pragma unroll
            for (int nf = 0; nf < 4; nf++) {
                int nr = warp_n * 32 + nf * 8 + (lane >> 2);
                int kc = kb + (lane & 3);
                b[nf][0] = Bs[nr][kc];
                b[nf][1] = Bs[nr][kc + 4];
            }
#pragma unroll
            for (int mf = 0; mf < 2; mf++)
#pragma unroll
                for (int nf = 0; nf < 4; nf++) {
                    asm volatile(
                        "mma.sync.aligned.m16n8k8.row.col.f32.tf32.tf32.f32 "
                        "{%0,%1,%2,%3}, {%4,%5,%6,%7}, {%8,%9}, {%0,%1,%2,%3};\n"
                        : "+f"(acc[mf][nf][0]), "+f"(acc[mf][nf][1]),
                          "+f"(acc[mf][nf][2]), "+f"(acc[mf][nf][3])
                        : "r"(a[mf][0]), "r"(a[mf][1]), "r"(a[mf][2]), "r"(a[mf][3]),
                          "r"(b[nf][0]), "r"(b[nf][1]));
                }
        }
        __syncthreads();
    }

    // Epilogue: c0 at (row, 2q), c1 (row, 2q+1), c2/c3 at row+8; q = lane&3
#pragma unroll
    for (int mf = 0; mf < 2; mf++) {
#pragma unroll
        for (int nf = 0; nf < 4; nf++) {
            int gr = bm + warp_m * 32 + mf * 16 + (lane >> 2);
            int gc = bn + warp_n * 32 + nf * 8 + 2 * (lane & 3);
            float b0 = 0.f, b1 = 0.f;
            if (BIAS) { b0 = __ldg(bias + gc); b1 = __ldg(bias + gc + 1); }
            if (gr < M) {
                float2 v = make_float2(acc[mf][nf][0] + b0, acc[mf][nf][1] + b1);
                *reinterpret_cast<float2*>(C + (size_t)gr * NTOT + gc) = v;
            }
            if (gr + 8 < M) {
                float2 v = make_float2(acc[mf][nf][2] + b0, acc[mf][nf][3] + b1);
                *reinterpret_cast<float2*>(C + (size_t)(gr + 8) * NTOT + gc) = v;
            }
        }
    }
}

// ---------------------------------------------------------------------------
// agg1[n][c] = b1[c]  (bias prefill; C must be power of two)
// ---------------------------------------------------------------------------
__global__ void init_bias(float* __restrict__ out, const float* __restrict__ b,
                          int total, int cmask) {
    int i = blockIdx.x * blockDim.x + threadIdx.x;
    int stride = gridDim.x * blockDim.x;
    for (; i < total; i += stride) out[i] = b[i & cmask];
}

// ---------------------------------------------------------------------------
// Edge scatter over 128-col rows (32 float4; exactly one float4 per lane).
// AGG[dst[e]] += (relu?)(H[src[e]]) via red.global.add.v4.f32 (no return trip).
// ---------------------------------------------------------------------------
template <bool RELU>
__global__ __launch_bounds__(256)
void scatter_add128(const float4* __restrict__ H, const int* __restrict__ ei,
                    float4* __restrict__ AGG, int E) {
    const int warp = (blockIdx.x * blockDim.x + threadIdx.x) >> 5;
    const int lane = threadIdx.x & 31;
    const int nwarps = (gridDim.x * blockDim.x) >> 5;
    const int* __restrict__ src = ei;
    const int* __restrict__ dst = ei + E;

    for (int e = warp; e < E; e += nwarps) {
        const int s = src[e];
        const int d = dst[e];
        if ((unsigned)s >= NN || (unsigned)d >= NN) continue;
        float4 v = __ldg(H + (size_t)s * 32 + lane);
        if (RELU) {
            v.x = fmaxf(v.x, 0.f); v.y = fmaxf(v.y, 0.f);
            v.z = fmaxf(v.z, 0.f); v.w = fmaxf(v.w, 0.f);
        }
        asm volatile(
            "red.global.add.v4.f32 [%0], {%1, %2, %3, %4};"
            :: "l"(AGG + (size_t)d * 32 + lane), "f"(v.x), "f"(v.y), "f"(v.z), "f"(v.w)
            : "memory");
    }
}

extern "C" void kernel_launch(void* const* d_in, const int* in_sizes, int n_in,
                              void* d_out, int out_size) {
    const float* x = (const float*)d_in[0];
    const int* edge_index = (const int*)d_in[1];
    const float* w1 = (const float*)d_in[2];
    const float* b1 = (const float*)d_in[3];
    const float* w2 = (const float*)d_in[4];
    const float* b2 = (const float*)d_in[5];
    float* out = (float*)d_out;

    float* h1;   cudaGetSymbolAddress((void**)&h1, g_h1);
    float* agg1; cudaGetSymbolAddress((void**)&agg1, g_agg1);
    float* agg2; cudaGetSymbolAddress((void**)&agg2, g_agg2);

    // h1 = x @ w1^T                       [50000,128], TF32 tensor cores
    {
        dim3 grid((NN + 127) / 128, HID_C / 64);
        gemm_tf32<IN_C, HID_C, false><<<grid, 256>>>(x, w1, nullptr, h1, NN);
    }
    // agg1 = broadcast(b1); agg1[dst] += h1[src]
    init_bias<<<1024, 256>>>(agg1, b1, NN * HID_C, HID_C - 1);
    scatter_add128<false><<<2048, 256>>>((const float4*)h1, edge_index,
                                         (float4*)agg1, EE);
    // agg2 = 0; agg2[dst] += relu(agg1[src])   (scatter BEFORE the wide GEMM:
    // A·(relu(agg1)@W2^T) == (A·relu(agg1))@W2^T — halves layer-2 scatter traffic)
    cudaMemsetAsync(agg2, 0, (size_t)NN * HID_C * sizeof(float));
    scatter_add128<true><<<2048, 256>>>((const float4*)agg1, edge_index,
                                        (float4*)agg2, EE);
    // out = agg2 @ w2^T + b2              [50000,256]
    {
        dim3 grid((NN + 127) / 128, OUT_C / 64);
        gemm_tf32<HID_C, OUT_C, true><<<grid, 256>>>(agg2, w2, b2, out, NN);
    }
}

// round 6
// speedup vs baseline: 2.4850x; 1.1269x over previous
#include <cuda_runtime.h>
#include <cstdint>

// Problem constants (fixed by the reference)
#define NN 50000
#define EE 800000
#define IN_C 512
#define HID_C 128
#define OUT_C 256

// Scratch (allocation-free rule: __device__ globals)
__device__ __align__(16) float g_h1[(size_t)NN * HID_C];    // x @ w1^T
__device__ __align__(16) float g_agg1[(size_t)NN * HID_C];  // A*h1 + b1
__device__ __align__(16) float g_agg2[(size_t)NN * HID_C];  // A*relu(agg1)

__device__ __forceinline__ uint32_t f2tf32(float f) {
    uint32_t r;
    asm("cvt.rna.tf32.f32 %0, %1;" : "=r"(r) : "f"(f));
    return r;
}

// ---------------------------------------------------------------------------
// TF32 tensor-core GEMM with 2-stage cp.async pipeline.
// C[m][n] = sum_k A[m][k] * W[n][k] (+ bias[n]);  W is [N,K] row-major.
// BM=128, BN=64, BK=32; 8 warps 4(M)x2(N); warp tile 32x32; mma m16n8k8.
// ---------------------------------------------------------------------------
template <int K, int NTOT, bool BIAS>
__global__ __launch_bounds__(256)
void gemm_tf32(const float* __restrict__ A, const float* __restrict__ W,
               const float* __restrict__ bias, float* __restrict__ C, int M) {
    constexpr int BM = 128, BN = 64, BK = 32, LDS = BK + 4;  // stride 36 floats
    constexpr int TILES = K / BK;
    __shared__ float As[2][BM][LDS];
    __shared__ float Bs[2][BN][LDS];

    const int tid = threadIdx.x;
    const int lane = tid & 31;
    const int wid = tid >> 5;
    const int warp_m = wid >> 1;   // 0..3
    const int warp_n = wid & 1;    // 0..1
    const int bm = blockIdx.x * BM;
    const int bn = blockIdx.y * BN;

    // Per-thread load coordinates
    const int a_row = tid >> 3;           // 0..31 (then +32 per rep)
    const int a_c4 = (tid & 7) * 4;

    float acc[2][4][4];
#pragma unroll
    for (int mf = 0; mf < 2; mf++)
#pragma unroll
        for (int nf = 0; nf < 4; nf++)
#pragma unroll
            for (int r = 0; r < 4; r++) acc[mf][nf][r] = 0.0f;

    auto load_stage = [&](int stage, int k0) {
        // A tile: 128 rows x 8 float4 -> 4 float4 per thread
#pragma unroll
        for (int i = 0; i < 4; i++) {
            int row = a_row + i * 32;
            const float* gp = A + (size_t)(bm + row) * K + k0 + a_c4;
            uint32_t sa = (uint32_t)__cvta_generic_to_shared(&As[stage][row][a_c4]);
            int sz = (bm + row < M) ? 16 : 0;   // zero-fill OOB rows
            asm volatile("cp.async.cg.shared.global [%0], [%1], 16, %2;"
                         :: "r"(sa), "l"(gp), "r"(sz));
        }
        // B tile: 64 rows x 8 float4 -> 2 float4 per thread
#pragma unroll
        for (int i = 0; i < 2; i++) {
            int row = a_row + i * 32;
            const float* gp = W + (size_t)(bn + row) * K + k0 + a_c4;
            uint32_t sa = (uint32_t)__cvta_generic_to_shared(&Bs[stage][row][a_c4]);
            asm volatile("cp.async.cg.shared.global [%0], [%1], 16;"
                         :: "r"(sa), "l"(gp));
        }
        asm volatile("cp.async.commit_group;");
    };

    load_stage(0, 0);

    for (int t = 0; t < TILES; t++) {
        const int buf = t & 1;
        if (t + 1 < TILES) {
            load_stage(buf ^ 1, (t + 1) * BK);
            asm volatile("cp.async.wait_group 1;");
        } else {
            asm volatile("cp.async.wait_group 0;");
        }
        __syncthreads();

#pragma unroll
        for (int ks = 0; ks < BK / 8; ks++) {
            const int kb = ks * 8;
            const int kc = kb + (lane & 3);
            uint32_t a[2][4], b[4][2];
#pragma unroll
            for (int mf = 0; mf < 2; mf++) {
                int mr = warp_m * 32 + mf * 16 + (lane >> 2);
                a[mf][0] = f2tf32(As[buf][mr][kc]);
                a[mf][1] = f2tf32(As[buf][mr + 8][kc]);
                a[mf][2] = f2tf32(As[buf][mr][kc + 4]);
                a[mf][3] = f2tf32(As[buf][mr + 8][kc + 4]);
            }
#pragma unroll
            for (int nf = 0; nf < 4; nf++) {
                int nr = warp_n * 32 + nf * 8 + (lane >> 2);
                b[nf][0] = f2tf32(Bs[buf][nr][kc]);
                b[nf][1] = f2tf32(Bs[buf][nr][kc + 4]);
            }
#pragma unroll
            for (int mf = 0; mf < 2; mf++)
#pragma unroll
                for (int nf = 0; nf < 4; nf++) {
                    asm volatile(
                        "mma.sync.aligned.m16n8k8.row.col.f32.tf32.tf32.f32 "
                        "{%0,%1,%2,%3}, {%4,%5,%6,%7}, {%8,%9}, {%0,%1,%2,%3};\n"
                        : "+f"(acc[mf][nf][0]), "+f"(acc[mf][nf][1]),
                          "+f"(acc[mf][nf][2]), "+f"(acc[mf][nf][3])
                        : "r"(a[mf][0]), "r"(a[mf][1]), "r"(a[mf][2]), "r"(a[mf][3]),
                          "r"(b[nf][0]), "r"(b[nf][1]));
                }
        }
        __syncthreads();
    }

    // Epilogue: c0 at (row, 2q), c1 (row, 2q+1), c2/c3 at row+8; q = lane&3
#pragma unroll
    for (int mf = 0; mf < 2; mf++) {
#pragma unroll
        for (int nf = 0; nf < 4; nf++) {
            int gr = bm + warp_m * 32 + mf * 16 + (lane >> 2);
            int gc = bn + warp_n * 32 + nf * 8 + 2 * (lane & 3);
            float b0 = 0.f, b1 = 0.f;
            if (BIAS) { b0 = __ldg(bias + gc); b1 = __ldg(bias + gc + 1); }
            if (gr < M) {
                float2 v = make_float2(acc[mf][nf][0] + b0, acc[mf][nf][1] + b1);
                *reinterpret_cast<float2*>(C + (size_t)gr * NTOT + gc) = v;
            }
            if (gr + 8 < M) {
                float2 v = make_float2(acc[mf][nf][2] + b0, acc[mf][nf][3] + b1);
                *reinterpret_cast<float2*>(C + (size_t)(gr + 8) * NTOT + gc) = v;
            }
        }
    }
}

// ---------------------------------------------------------------------------
// out[n][c] = b[c], float4 vectorized. c4mask = (C/4 - 1), power of two.
// ---------------------------------------------------------------------------
__global__ void init_bias4(float4* __restrict__ out, const float4* __restrict__ b,
                           int total4, int c4mask) {
    int i = blockIdx.x * blockDim.x + threadIdx.x;
    int stride = gridDim.x * blockDim.x;
    for (; i < total4; i += stride) out[i] = b[i & c4mask];
}

// ---------------------------------------------------------------------------
// Edge scatter over 128-col rows (one float4 per lane), 2x unrolled for MLP.
// AGG[dst[e]] += (relu?)(H[src[e]]) via red.global.add.v4.f32.
// ---------------------------------------------------------------------------
template <bool RELU>
__device__ __forceinline__ float4 maybe_relu(float4 v) {
    if (RELU) {
        v.x = fmaxf(v.x, 0.f); v.y = fmaxf(v.y, 0.f);
        v.z = fmaxf(v.z, 0.f); v.w = fmaxf(v.w, 0.f);
    }
    return v;
}

template <bool RELU>
__global__ __launch_bounds__(256)
void scatter_add128(const float4* __restrict__ H, const int* __restrict__ ei,
                    float4* __restrict__ AGG, int E) {
    const int warp = (blockIdx.x * blockDim.x + threadIdx.x) >> 5;
    const int lane = threadIdx.x & 31;
    const int nwarps = (gridDim.x * blockDim.x) >> 5;
    const int* __restrict__ src = ei;
    const int* __restrict__ dst = ei + E;

    int e = warp;
    for (; e + nwarps < E; e += 2 * nwarps) {
        const int e1 = e + nwarps;
        const int s0 = src[e],  d0 = dst[e];
        const int s1 = src[e1], d1 = dst[e1];
        float4 v0 = __ldg(H + (size_t)s0 * 32 + lane);
        float4 v1 = __ldg(H + (size_t)s1 * 32 + lane);
        v0 = maybe_relu<RELU>(v0);
        v1 = maybe_relu<RELU>(v1);
        asm volatile("red.global.add.v4.f32 [%0], {%1, %2, %3, %4};"
                     :: "l"(AGG + (size_t)d0 * 32 + lane),
                        "f"(v0.x), "f"(v0.y), "f"(v0.z), "f"(v0.w) : "memory");
        asm volatile("red.global.add.v4.f32 [%0], {%1, %2, %3, %4};"
                     :: "l"(AGG + (size_t)d1 * 32 + lane),
                        "f"(v1.x), "f"(v1.y), "f"(v1.z), "f"(v1.w) : "memory");
    }
    if (e < E) {
        const int s = src[e], d = dst[e];
        float4 v = maybe_relu<RELU>(__ldg(H + (size_t)s * 32 + lane));
        asm volatile("red.global.add.v4.f32 [%0], {%1, %2, %3, %4};"
                     :: "l"(AGG + (size_t)d * 32 + lane),
                        "f"(v.x), "f"(v.y), "f"(v.z), "f"(v.w) : "memory");
    }
}

extern "C" void kernel_launch(void* const* d_in, const int* in_sizes, int n_in,
                              void* d_out, int out_size) {
    const float* x = (const float*)d_in[0];
    const int* edge_index = (const int*)d_in[1];
    const float* w1 = (const float*)d_in[2];
    const float* b1 = (const float*)d_in[3];
    const float* w2 = (const float*)d_in[4];
    const float* b2 = (const float*)d_in[5];
    float* out = (float*)d_out;

    float* h1;   cudaGetSymbolAddress((void**)&h1, g_h1);
    float* agg1; cudaGetSymbolAddress((void**)&agg1, g_agg1);
    float* agg2; cudaGetSymbolAddress((void**)&agg2, g_agg2);

    // h1 = x @ w1^T                       [50000,128], TF32 + cp.async pipeline
    {
        dim3 grid((NN + 127) / 128, HID_C / 64);
        gemm_tf32<IN_C, HID_C, false><<<grid, 256>>>(x, w1, nullptr, h1, NN);
    }
    // agg1 = broadcast(b1); agg1[dst] += h1[src]
    init_bias4<<<512, 256>>>((float4*)agg1, (const float4*)b1,
                             NN * HID_C / 4, HID_C / 4 - 1);
    scatter_add128<false><<<2048, 256>>>((const float4*)h1, edge_index,
                                         (float4*)agg1, EE);
    // agg2 = 0; agg2[dst] += relu(agg1[src])
    // (scatter BEFORE the wide GEMM: A·(relu(agg1)@W2^T) == (A·relu(agg1))@W2^T)
    cudaMemsetAsync(agg2, 0, (size_t)NN * HID_C * sizeof(float));
    scatter_add128<true><<<2048, 256>>>((const float4*)agg1, edge_index,
                                        (float4*)agg2, EE);
    // out = agg2 @ w2^T + b2              [50000,256]
    {
        dim3 grid((NN + 127) / 128, OUT_C / 64);
        gemm_tf32<HID_C, OUT_C, true><<<grid, 256>>>(agg2, w2, b2, out, NN);
    }
}